// round 4
// baseline (speedup 1.0000x reference)
#include <cuda_runtime.h>
#include <cstdint>
#include <math.h>

#define NN 8192
#define FF 64
#define HH 128
#define RR 3
#define DEG 32
#define KK 32
#define EE (NN*DEG)
#define NEG 0.2f

// ------------------------- device scratch (no cudaMalloc allowed) ----------
__device__ float g_SAhi[NN*HH], g_SAlo[NN*HH];   // x@Ws1[0:64]   (compensated)
__device__ float g_SBhi[NN*HH], g_SBlo[NN*HH];   // x@Ws1[64:128] (compensated)
__device__ float g_PA[NN*HH];                    // x@Wp[0:64] + bp
__device__ float g_PB[NN*HH];                    // x@Wp[64:128]
__device__ float g_Wg1T[RR*64*HH];               // Wg1 transposed to [r][m][h]
__device__ double g_gspart[128*FF];
__device__ double g_cpart[128];
__device__ double g_rp[RR];
__device__ double g_amp;

// ---- error-free float helpers (guard against fma contraction) -------------
__device__ __forceinline__ void twosum(float a, float b, float& s, float& e) {
    s = __fadd_rn(a, b);
    float bb = __fsub_rn(s, a);
    e = __fadd_rn(__fsub_rn(a, __fsub_rn(s, bb)), __fsub_rn(b, bb));
}
__device__ __forceinline__ void kadd(float& s, float& c, float v) {
    float t, e;
    twosum(s, v, t, e);
    s = t; c = __fadd_rn(c, e);
}
__device__ __forceinline__ void kprodadd(float& s, float& c, float a, float b) {
    float p = __fmul_rn(a, b);
    float ep = fmaf(a, b, -p);
    float t, e;
    twosum(s, p, t, e);
    s = t; c = __fadd_rn(c, __fadd_rn(e, ep));
}

// ------------------------- kernel A: global stats partials ------------------
__global__ void stats_kernel(const float* __restrict__ x,
                             const float* __restrict__ Wc1, const float* __restrict__ bc1,
                             const float* __restrict__ Wc2, const float* __restrict__ bc2)
{
    __shared__ float xs[FF];
    __shared__ float red[HH];
    int j = threadIdx.x;            // 128 threads
    double gacc = 0.0, csum = 0.0;
    int base = blockIdx.x * 64;
    for (int nd = 0; nd < 64; nd++) {
        int n = base + nd;
        if (j < FF) xs[j] = x[n*FF + j];
        __syncthreads();
        if (j < FF) gacc += (double)xs[j];
        float acc = bc1[j];
        #pragma unroll
        for (int f = 0; f < FF; f++) acc = fmaf(xs[f], Wc1[f*HH + j], acc);
        acc = fmaxf(acc, 0.f) * Wc2[j];
        red[j] = acc;
        __syncthreads();
        for (int s = 64; s > 0; s >>= 1) { if (j < s) red[j] += red[j+s]; __syncthreads(); }
        if (j == 0) {
            double z = (double)red[0] + (double)bc2[0];
            csum += 1.0/(1.0+exp(-z));
        }
        __syncthreads();
    }
    if (j < FF) g_gspart[blockIdx.x*FF + j] = gacc;
    if (j == 0) g_cpart[blockIdx.x] = csum;
}

// ------------------------- kernel B: finalize scalars + Wg1 transpose -------
__global__ void setup_kernel(const float* __restrict__ Wr1, const float* __restrict__ br1,
                             const float* __restrict__ Wr2, const float* __restrict__ br2,
                             const float* __restrict__ Wg1)
{
    __shared__ double gs[FF];
    __shared__ double red[HH];
    __shared__ double hr[HH];
    __shared__ double slog[RR];
    int j = threadIdx.x;            // 128 threads
    if (j < FF) {
        double s = 0.0;
        for (int b = 0; b < 128; b++) s += g_gspart[b*FF + j];
        gs[j] = s * (1.0/(double)NN);
    }
    if (j == 0) {
        double c = 0.0;
        for (int b = 0; b < 128; b++) c += g_cpart[b];
        g_amp = 1.0 + 0.5 * (c * (1.0/(double)NN));
    }
    __syncthreads();
    double a = (double)br1[j];
    for (int f = 0; f < FF; f++) a += gs[f] * (double)Wr1[f*HH + j];
    hr[j] = a > 0.0 ? a : 0.0;
    __syncthreads();
    for (int r = 0; r < RR; r++) {
        red[j] = hr[j] * (double)Wr2[j*RR + r];
        __syncthreads();
        for (int s = 64; s > 0; s >>= 1) { if (j < s) red[j] += red[j+s]; __syncthreads(); }
        if (j == 0) slog[r] = red[0] + (double)br2[r];
        __syncthreads();
    }
    if (j == 0) {
        double m = fmax(slog[0], fmax(slog[1], slog[2]));
        double e0 = exp(slog[0]-m), e1 = exp(slog[1]-m), e2 = exp(slog[2]-m);
        double inv = 1.0/(e0+e1+e2);
        g_rp[0]=e0*inv; g_rp[1]=e1*inv; g_rp[2]=e2*inv;
    }
    // transpose Wg1 [R][H][64] -> [R][64][H]
    for (int i = j; i < RR*64*HH; i += blockDim.x) {
        int r   = i / (64*HH);
        int rem = i - r*64*HH;
        int m   = rem / HH;
        int hh  = rem - m*HH;
        g_Wg1T[i] = Wg1[(r*HH + hh)*64 + m];
    }
}

// ------------------------- kernel C: per-node precompute --------------------
__global__ void node_pre_kernel(const float* __restrict__ x,
                                const float* __restrict__ Ws1,
                                const float* __restrict__ Wp,  const float* __restrict__ bp)
{
    __shared__ float xs[8][FF];
    int t = threadIdx.x;            // 256 threads, 8 nodes/block
    int n0 = blockIdx.x * 8;
    for (int i = t; i < 8*FF; i += 256) xs[i/FF][i%FF] = x[n0*FF + i];
    __syncthreads();
    int jc = t & 127;
    int rowoff = (t < 128) ? 0 : FF;
    const float* W1 = Ws1 + rowoff*HH + jc;
    const float* W2 = Wp  + rowoff*HH + jc;
    float sS[8], cS[8], accP[8];
    #pragma unroll
    for (int n = 0; n < 8; n++) { sS[n] = 0.f; cS[n] = 0.f; accP[n] = 0.f; }
    for (int f = 0; f < FF; f++) {
        float w1 = W1[f*HH], w2 = W2[f*HH];
        #pragma unroll
        for (int n = 0; n < 8; n++) {
            float xv = xs[n][f];
            kprodadd(sS[n], cS[n], xv, w1);      // compensated scorer dot
            accP[n] = fmaf(xv, w2, accP[n]);     // plain gating dot
        }
    }
    if (t < 128) {
        float b2 = bp[jc];
        #pragma unroll
        for (int n = 0; n < 8; n++) {
            g_SAhi[(n0+n)*HH + jc] = sS[n];
            g_SAlo[(n0+n)*HH + jc] = cS[n];
            g_PA[(n0+n)*HH + jc]   = accP[n] + b2;
        }
    } else {
        #pragma unroll
        for (int n = 0; n < 8; n++) {
            g_SBhi[(n0+n)*HH + jc] = sS[n];
            g_SBlo[(n0+n)*HH + jc] = cS[n];
            g_PB[(n0+n)*HH + jc]   = accP[n];
        }
    }
}

// ------------------------- kernel E: fused edge scorer + row top-k ----------
// smem layout (floats)
#define OFF_W     0          // [3][64][128] = 24576
#define OFF_WS1C  24576      // Ws1 rows 128..130  [3][128]
#define OFF_WPC   24960      // Wp  rows 128..130  [3][128]
#define OFF_LNG   25344
#define OFF_LNB   25472
#define OFF_WS2   25600
#define OFF_WG2   25728      // [3][64]
#define OFF_BG1   25920      // [3][64]
#define OFF_BS1   26112      // [128]
#define SMEM_FLOATS 26240

// compensated per-element h = SA + SB + a0*w0 + a1*w1 + a2*w2 + b, rounded once
__device__ __forceinline__ float comp_h(float shi, float slo, float thi, float tlo,
                                        float a0, float w0, float a1, float w1,
                                        float a2, float w2, float b)
{
    float s, c, e;
    twosum(shi, thi, s, e);
    c = __fadd_rn(e, __fadd_rn(slo, tlo));
    kprodadd(s, c, a0, w0);
    kprodadd(s, c, a1, w1);
    kprodadd(s, c, a2, w2);
    kadd(s, c, b);
    return __fadd_rn(s, c);
}

__global__ void __launch_bounds__(256, 1)
edge_kernel(const void* __restrict__ ei, const float* __restrict__ attr,
            const float* __restrict__ Ws1, const float* __restrict__ Wp,
            const float* __restrict__ lng, const float* __restrict__ lnb,
            const float* __restrict__ Ws2, const float* __restrict__ bs2,
            const float* __restrict__ bs1, const float* __restrict__ bg1,
            const float* __restrict__ Wg2, const float* __restrict__ bg2,
            float* __restrict__ out, int out_size)
{
    extern __shared__ float sm[];
    float* sW    = sm + OFF_W;
    float* sWs1c = sm + OFF_WS1C;
    float* sWpc  = sm + OFF_WPC;
    float* sLng  = sm + OFF_LNG;
    float* sLnb  = sm + OFF_LNB;
    float* sWs2  = sm + OFF_WS2;
    float* sWg2  = sm + OFF_WG2;
    float* sbg1  = sm + OFF_BG1;
    float* sBs1  = sm + OFF_BS1;

    int t = threadIdx.x;
    for (int i = t; i < RR*64*HH; i += 256) sW[i] = g_Wg1T[i];
    for (int i = t; i < 3*HH; i += 256) { sWs1c[i] = Ws1[HH*HH + i]; sWpc[i] = Wp[HH*HH + i]; }
    if (t < HH) { sLng[t] = lng[t]; sLnb[t] = lnb[t]; sWs2[t] = Ws2[t]; sBs1[t] = bs1[t]; }
    if (t < RR*64) { sWg2[t] = Wg2[t]; sbg1[t] = bg1[t]; }
    __syncthreads();

    int warp = t >> 5, lane = t & 31;
    int src = blockIdx.x * 8 + warp;
    int e = src * DEG + lane;

    // detect int64 vs int32 edge_index layout
    const int* eiw = (const int*)ei;
    int tgt;
    if (eiw[65] == 0) tgt = (int)(((const long long*)ei)[EE + e]);
    else              tgt = eiw[EE + e];

    float a0 = attr[e*3+0], a1 = attr[e*3+1], a2 = attr[e*3+2];

    const float4* SAh4 = (const float4*)(g_SAhi + src*HH);
    const float4* SAl4 = (const float4*)(g_SAlo + src*HH);
    const float4* SBh4 = (const float4*)(g_SBhi + (size_t)tgt*HH);
    const float4* SBl4 = (const float4*)(g_SBlo + (size_t)tgt*HH);
    const float4* c0   = (const float4*)sWs1c;
    const float4* c1   = (const float4*)(sWs1c + HH);
    const float4* c2   = (const float4*)(sWs1c + 2*HH);
    const float4* bb4  = (const float4*)sBs1;

    float4 h4[32];
    float ms = 0.f, mc = 0.f;     // Kahan mean accumulator
    #pragma unroll
    for (int q = 0; q < 32; q++) {
        float4 sh = SAh4[q], sl = SAl4[q], th = SBh4[q], tl = SBl4[q];
        float4 w0 = c0[q], w1 = c1[q], w2 = c2[q], bb = bb4[q];
        float4 v;
        v.x = comp_h(sh.x, sl.x, th.x, tl.x, a0,w0.x, a1,w1.x, a2,w2.x, bb.x);
        v.y = comp_h(sh.y, sl.y, th.y, tl.y, a0,w0.y, a1,w1.y, a2,w2.y, bb.y);
        v.z = comp_h(sh.z, sl.z, th.z, tl.z, a0,w0.z, a1,w1.z, a2,w2.z, bb.z);
        v.w = comp_h(sh.w, sl.w, th.w, tl.w, a0,w0.w, a1,w1.w, a2,w2.w, bb.w);
        h4[q] = v;
        kadd(ms, mc, v.x); kadd(ms, mc, v.y); kadd(ms, mc, v.z); kadd(ms, mc, v.w);
    }
    float mu = __fmul_rn(__fadd_rn(ms, mc), 0.0078125f);   // /128 exact scale
    float vs = 0.f, vc = 0.f;
    #pragma unroll
    for (int q = 0; q < 32; q++) {
        float d;
        d = __fsub_rn(h4[q].x, mu); kprodadd(vs, vc, d, d);
        d = __fsub_rn(h4[q].y, mu); kprodadd(vs, vc, d, d);
        d = __fsub_rn(h4[q].z, mu); kprodadd(vs, vc, d, d);
        d = __fsub_rn(h4[q].w, mu); kprodadd(vs, vc, d, d);
    }
    float var = __fmul_rn(__fadd_rn(vs, vc), 0.0078125f);
    float vpe = __fadd_rn(var, 1e-5f);
    float rstd = (float)(1.0 / sqrt((double)vpe));          // correctly-rounded rsqrt

    float rs = 0.f, rc = 0.f;     // Kahan for raw dot
    const float4* g4 = (const float4*)sLng;
    const float4* b4 = (const float4*)sLnb;
    const float4* s4 = (const float4*)sWs2;
    #pragma unroll
    for (int q = 0; q < 32; q++) {
        float4 gg = g4[q], bb = b4[q], ww = s4[q];
        float u;
        u = __fadd_rn(__fmul_rn(__fmul_rn(__fsub_rn(h4[q].x, mu), rstd), gg.x), bb.x);
        u = (u >= 0.f) ? u : __fmul_rn(NEG, u); kprodadd(rs, rc, u, ww.x);
        u = __fadd_rn(__fmul_rn(__fmul_rn(__fsub_rn(h4[q].y, mu), rstd), gg.y), bb.y);
        u = (u >= 0.f) ? u : __fmul_rn(NEG, u); kprodadd(rs, rc, u, ww.y);
        u = __fadd_rn(__fmul_rn(__fmul_rn(__fsub_rn(h4[q].z, mu), rstd), gg.z), bb.z);
        u = (u >= 0.f) ? u : __fmul_rn(NEG, u); kprodadd(rs, rc, u, ww.z);
        u = __fadd_rn(__fmul_rn(__fmul_rn(__fsub_rn(h4[q].w, mu), rstd), gg.w), bb.w);
        u = (u >= 0.f) ? u : __fmul_rn(NEG, u); kprodadd(rs, rc, u, ww.w);
    }
    kadd(rs, rc, bs2[0]);
    float raw = __fadd_rn(rs, rc);

    // edge_hidden = relu(PA[src] + PB[tgt] + attr@Wp_c)  -> reuse h4 regs
    const float4* PA4 = (const float4*)(g_PA + src*HH);
    const float4* PB4 = (const float4*)(g_PB + (size_t)tgt*HH);
    const float4* p0  = (const float4*)sWpc;
    const float4* p1  = (const float4*)(sWpc + HH);
    const float4* p2  = (const float4*)(sWpc + 2*HH);
    #pragma unroll
    for (int q = 0; q < 32; q++) {
        float4 pa = PA4[q], pb = PB4[q];
        float4 w0 = p0[q], w1 = p1[q], w2 = p2[q];
        float4 v;
        v.x = fmaxf(pa.x + pb.x + fmaf(a0, w0.x, fmaf(a1, w1.x, a2*w2.x)), 0.f);
        v.y = fmaxf(pa.y + pb.y + fmaf(a0, w0.y, fmaf(a1, w1.y, a2*w2.y)), 0.f);
        v.z = fmaxf(pa.z + pb.z + fmaf(a0, w0.z, fmaf(a1, w1.z, a2*w2.z)), 0.f);
        v.w = fmaxf(pa.w + pb.w + fmaf(a0, w0.w, fmaf(a1, w1.w, a2*w2.w)), 0.f);
        h4[q] = v;
    }

    // regime gating (plain f32 einsum; error attenuated via sigmoid + small Wg2)
    double gc = 0.0;
    for (int r = 0; r < RR; r++) {
        float gsum = 0.f;
        const float4* Wr = (const float4*)(sW + r*64*HH);
        for (int m = 0; m < 64; m += 2) {
            const float4* wA = Wr + m*32;
            const float4* wB = Wr + (m+1)*32;
            float d0 = sbg1[r*64 + m];
            float d1 = sbg1[r*64 + m + 1];
            #pragma unroll
            for (int q = 0; q < 32; q++) {
                float4 ev = h4[q];
                float4 wa = wA[q], wb = wB[q];
                d0 = fmaf(ev.x, wa.x, d0); d1 = fmaf(ev.x, wb.x, d1);
                d0 = fmaf(ev.y, wa.y, d0); d1 = fmaf(ev.y, wb.y, d1);
                d0 = fmaf(ev.z, wa.z, d0); d1 = fmaf(ev.z, wb.z, d1);
                d0 = fmaf(ev.w, wa.w, d0); d1 = fmaf(ev.w, wb.w, d1);
            }
            d0 = fmaxf(d0, 0.f); d1 = fmaxf(d1, 0.f);
            gsum = fmaf(d0, sWg2[r*64 + m], gsum);
            gsum = fmaf(d1, sWg2[r*64 + m + 1], gsum);
        }
        double z = (double)gsum + (double)bg2[r];
        double gate = 1.0/(1.0 + exp(-z));
        gc += gate * g_rp[r];
    }

    float gc_f  = (float)gc;
    float amp_f = (float)g_amp;
    float score = __fmul_rn(__fmul_rn(raw, gc_f), amp_f);
    float logit = __fdiv_rn(score, 0.3f);       // jax divides by TEMP

    // ---------------- row finale (warp == one source row) -------------------
    const unsigned full = 0xffffffffu;
    unsigned dupm = __match_any_sync(full, tgt);
    int leader = 31 - __clz(dupm);          // highest lane = last edge wins
    bool valid = (lane == leader);
    unsigned vmask = __ballot_sync(full, valid);

    float lv = valid ? logit : -3.4e38f;
    float mx = lv;
    #pragma unroll
    for (int o = 16; o; o >>= 1) mx = fmaxf(mx, __shfl_xor_sync(full, mx, o));
    float evf = 0.f;
    if (valid) {
        float d = __fsub_rn(logit, mx);
        evf = (float)exp((double)d);        // correctly-rounded float exp
    }
    double sumd = (double)evf;
    #pragma unroll
    for (int o = 16; o; o >>= 1) sumd += __shfl_xor_sync(full, sumd, o);

    // occupancy of target indices < 64 (for zero-fill slots)
    unsigned long long occ = (tgt < 64) ? (1ull << tgt) : 0ull;
    #pragma unroll
    for (int o = 16; o; o >>= 1) occ |= __shfl_xor_sync(full, occ, o);

    float p; int idx;
    if (valid) {
        p = (float)((double)evf / sumd);
        idx = tgt;
    } else {
        // q-th smallest column index not present in the target set
        int q = __popc(~vmask & ((1u << lane) - 1u));
        unsigned long long miss = ~occ;
        unsigned lo = (unsigned)miss;
        int pl = __popc(lo);
        unsigned word; int base2; int cnt = q;
        if (cnt < pl) { word = lo; base2 = 0; }
        else { word = (unsigned)(miss >> 32); base2 = 32; cnt -= pl; }
        while (cnt > 0) { word &= word - 1u; cnt--; }
        idx = base2 + (__ffs(word) - 1);
        p = 0.f;
    }

    // bitonic sort 32 lanes: value desc, tie -> smaller index (lax.top_k rule)
    #pragma unroll
    for (int k = 2; k <= 32; k <<= 1) {
        #pragma unroll
        for (int jj = k >> 1; jj > 0; jj >>= 1) {
            float p2 = __shfl_xor_sync(full, p, jj);
            int   i2 = __shfl_xor_sync(full, idx, jj);
            bool mineBetter = (p > p2) || (p == p2 && idx < i2);
            bool lower = ((lane & jj) == 0);
            bool up    = ((lane & k) == 0);
            bool keepBetter = (lower == up);
            if (keepBetter != mineBetter) { p = p2; idx = i2; }
        }
    }

    float w = (p > 1e-6f) ? p : 0.f;
    int o0 = src * KK + lane;
    out[o0] = w;
    if (out_size >= 2*NN*KK) out[NN*KK + o0] = (float)idx;
}

// ------------------------- launch ------------------------------------------
extern "C" void kernel_launch(void* const* d_in, const int* in_sizes, int n_in,
                              void* d_out, int out_size)
{
    const float* x   = (const float*)d_in[0];
    const void*  ei  = d_in[1];
    const float* att = (const float*)d_in[2];
    const float* Ws1 = (const float*)d_in[3];
    const float* bs1 = (const float*)d_in[4];
    const float* lng = (const float*)d_in[5];
    const float* lnb = (const float*)d_in[6];
    const float* Ws2 = (const float*)d_in[7];
    const float* bs2 = (const float*)d_in[8];
    const float* Wp  = (const float*)d_in[9];
    const float* bp  = (const float*)d_in[10];
    const float* Wr1 = (const float*)d_in[11];
    const float* br1 = (const float*)d_in[12];
    const float* Wr2 = (const float*)d_in[13];
    const float* br2 = (const float*)d_in[14];
    const float* Wg1 = (const float*)d_in[15];
    const float* bg1 = (const float*)d_in[16];
    const float* Wg2 = (const float*)d_in[17];
    const float* bg2 = (const float*)d_in[18];
    const float* Wc1 = (const float*)d_in[19];
    const float* bc1 = (const float*)d_in[20];
    const float* Wc2 = (const float*)d_in[21];
    const float* bc2 = (const float*)d_in[22];

    cudaFuncSetAttribute(edge_kernel, cudaFuncAttributeMaxDynamicSharedMemorySize,
                         SMEM_FLOATS * (int)sizeof(float));

    stats_kernel<<<128, 128>>>(x, Wc1, bc1, Wc2, bc2);
    setup_kernel<<<1, 128>>>(Wr1, br1, Wr2, br2, Wg1);
    node_pre_kernel<<<1024, 256>>>(x, Ws1, Wp, bp);
    edge_kernel<<<1024, 256, SMEM_FLOATS * sizeof(float)>>>(
        ei, att, Ws1, Wp, lng, lnb, Ws2, bs2, bs1, bg1, Wg2, bg2,
        (float*)d_out, out_size);
}

// round 5
// speedup vs baseline: 1.0300x; 1.0300x over previous
#include <cuda_runtime.h>
#include <cstdint>
#include <math.h>

#define NN 8192
#define FF 64
#define HH 128
#define RR 3
#define DEG 32
#define KK 32
#define EE (NN*DEG)
#define NEG 0.2f

typedef unsigned long long ull;

// ------------------------- device scratch (no cudaMalloc allowed) ----------
__device__ float g_SAhi[NN*HH], g_SAlo[NN*HH];   // x@Ws1[0:64]   (compensated)
__device__ float g_SBhi[NN*HH], g_SBlo[NN*HH];   // x@Ws1[64:128] (compensated)
__device__ float g_PA[NN*HH];                    // x@Wp[0:64] + bp
__device__ float g_PB[NN*HH];                    // x@Wp[64:128]
__device__ float g_Wg1KM[HH*192];                // Wg1 as [k][r*64+m]
__device__ float g_raw[EE];                      // scorer raw per edge
__device__ double g_gspart[128*FF];
__device__ double g_cpart[128];
__device__ double g_rp[RR];
__device__ double g_amp;

// ---- error-free float helpers (guard against fma contraction) -------------
__device__ __forceinline__ void twosum(float a, float b, float& s, float& e) {
    s = __fadd_rn(a, b);
    float bb = __fsub_rn(s, a);
    e = __fadd_rn(__fsub_rn(a, __fsub_rn(s, bb)), __fsub_rn(b, bb));
}
__device__ __forceinline__ void kadd(float& s, float& c, float v) {
    float t, e;
    twosum(s, v, t, e);
    s = t; c = __fadd_rn(c, e);
}
__device__ __forceinline__ void kprodadd(float& s, float& c, float a, float b) {
    float p = __fmul_rn(a, b);
    float ep = fmaf(a, b, -p);
    float t, e;
    twosum(s, p, t, e);
    s = t; c = __fadd_rn(c, __fadd_rn(e, ep));
}

// ---- packed f32x2 helpers --------------------------------------------------
__device__ __forceinline__ ull pack2(float lo, float hi) {
    ull r; asm("mov.b64 %0, {%1, %2};" : "=l"(r) : "f"(lo), "f"(hi)); return r;
}
__device__ __forceinline__ float2 unpack2(ull v) {
    float2 q; asm("mov.b64 {%0, %1}, %2;" : "=f"(q.x), "=f"(q.y) : "l"(v)); return q;
}
#define FFMA2(d, a, b) asm("fma.rn.f32x2 %0, %1, %2, %0;" : "+l"(d) : "l"(a), "l"(b))

// ------------------------- kernel A: global stats partials ------------------
__global__ void stats_kernel(const float* __restrict__ x,
                             const float* __restrict__ Wc1, const float* __restrict__ bc1,
                             const float* __restrict__ Wc2, const float* __restrict__ bc2)
{
    __shared__ float xs[FF];
    __shared__ float red[HH];
    int j = threadIdx.x;            // 128 threads
    double gacc = 0.0, csum = 0.0;
    int base = blockIdx.x * 64;
    for (int nd = 0; nd < 64; nd++) {
        int n = base + nd;
        if (j < FF) xs[j] = x[n*FF + j];
        __syncthreads();
        if (j < FF) gacc += (double)xs[j];
        float acc = bc1[j];
        #pragma unroll
        for (int f = 0; f < FF; f++) acc = fmaf(xs[f], Wc1[f*HH + j], acc);
        acc = fmaxf(acc, 0.f) * Wc2[j];
        red[j] = acc;
        __syncthreads();
        for (int s = 64; s > 0; s >>= 1) { if (j < s) red[j] += red[j+s]; __syncthreads(); }
        if (j == 0) {
            double z = (double)red[0] + (double)bc2[0];
            csum += 1.0/(1.0+exp(-z));
        }
        __syncthreads();
    }
    if (j < FF) g_gspart[blockIdx.x*FF + j] = gacc;
    if (j == 0) g_cpart[blockIdx.x] = csum;
}

// ------------------------- kernel B: finalize scalars + Wg1 transpose -------
__global__ void setup_kernel(const float* __restrict__ Wr1, const float* __restrict__ br1,
                             const float* __restrict__ Wr2, const float* __restrict__ br2,
                             const float* __restrict__ Wg1)
{
    __shared__ double gs[FF];
    __shared__ double red[HH];
    __shared__ double hr[HH];
    __shared__ double slog[RR];
    int j = threadIdx.x;            // 128 threads
    if (j < FF) {
        double s = 0.0;
        for (int b = 0; b < 128; b++) s += g_gspart[b*FF + j];
        gs[j] = s * (1.0/(double)NN);
    }
    if (j == 0) {
        double c = 0.0;
        for (int b = 0; b < 128; b++) c += g_cpart[b];
        g_amp = 1.0 + 0.5 * (c * (1.0/(double)NN));
    }
    __syncthreads();
    double a = (double)br1[j];
    for (int f = 0; f < FF; f++) a += gs[f] * (double)Wr1[f*HH + j];
    hr[j] = a > 0.0 ? a : 0.0;
    __syncthreads();
    for (int r = 0; r < RR; r++) {
        red[j] = hr[j] * (double)Wr2[j*RR + r];
        __syncthreads();
        for (int s = 64; s > 0; s >>= 1) { if (j < s) red[j] += red[j+s]; __syncthreads(); }
        if (j == 0) slog[r] = red[0] + (double)br2[r];
        __syncthreads();
    }
    if (j == 0) {
        double m = fmax(slog[0], fmax(slog[1], slog[2]));
        double e0 = exp(slog[0]-m), e1 = exp(slog[1]-m), e2 = exp(slog[2]-m);
        double inv = 1.0/(e0+e1+e2);
        g_rp[0]=e0*inv; g_rp[1]=e1*inv; g_rp[2]=e2*inv;
    }
    // transpose Wg1 [R][H][64] -> [k=H][r*64+m]
    for (int i = j; i < HH*192; i += blockDim.x) {
        int h  = i / 192;
        int rm = i - h*192;
        int r  = rm >> 6;
        int m  = rm & 63;
        g_Wg1KM[i] = Wg1[(r*HH + h)*64 + m];
    }
}

// ------------------------- kernel C: per-node precompute --------------------
__global__ void node_pre_kernel(const float* __restrict__ x,
                                const float* __restrict__ Ws1,
                                const float* __restrict__ Wp,  const float* __restrict__ bp)
{
    __shared__ float xs[8][FF];
    int t = threadIdx.x;            // 256 threads, 8 nodes/block
    int n0 = blockIdx.x * 8;
    for (int i = t; i < 8*FF; i += 256) xs[i/FF][i%FF] = x[n0*FF + i];
    __syncthreads();
    int jc = t & 127;
    int rowoff = (t < 128) ? 0 : FF;
    const float* W1 = Ws1 + rowoff*HH + jc;
    const float* W2 = Wp  + rowoff*HH + jc;
    float sS[8], cS[8], accP[8];
    #pragma unroll
    for (int n = 0; n < 8; n++) { sS[n] = 0.f; cS[n] = 0.f; accP[n] = 0.f; }
    for (int f = 0; f < FF; f++) {
        float w1 = W1[f*HH], w2 = W2[f*HH];
        #pragma unroll
        for (int n = 0; n < 8; n++) {
            float xv = xs[n][f];
            kprodadd(sS[n], cS[n], xv, w1);      // compensated scorer dot
            accP[n] = fmaf(xv, w2, accP[n]);     // plain gating dot
        }
    }
    if (t < 128) {
        float b2 = bp[jc];
        #pragma unroll
        for (int n = 0; n < 8; n++) {
            g_SAhi[(n0+n)*HH + jc] = sS[n];
            g_SAlo[(n0+n)*HH + jc] = cS[n];
            g_PA[(n0+n)*HH + jc]   = accP[n] + b2;
        }
    } else {
        #pragma unroll
        for (int n = 0; n < 8; n++) {
            g_SBhi[(n0+n)*HH + jc] = sS[n];
            g_SBlo[(n0+n)*HH + jc] = cS[n];
            g_PB[(n0+n)*HH + jc]   = accP[n];
        }
    }
}

// compensated per-element h = SA + SB + a0*w0 + a1*w1 + a2*w2 + b, rounded once
__device__ __forceinline__ float comp_h(float shi, float slo, float thi, float tlo,
                                        float a0, float w0, float a1, float w1,
                                        float a2, float w2, float b)
{
    float s, c, e;
    twosum(shi, thi, s, e);
    c = __fadd_rn(e, __fadd_rn(slo, tlo));
    kprodadd(s, c, a0, w0);
    kprodadd(s, c, a1, w1);
    kprodadd(s, c, a2, w2);
    kadd(s, c, b);
    return __fadd_rn(s, c);
}

// ------------------------- kernel E1: scorer (raw per edge) -----------------
__global__ void __launch_bounds__(256, 1)
scorer_kernel(const void* __restrict__ ei, const float* __restrict__ attr,
              const float* __restrict__ Ws1,
              const float* __restrict__ lng, const float* __restrict__ lnb,
              const float* __restrict__ Ws2, const float* __restrict__ bs2,
              const float* __restrict__ bs1)
{
    __shared__ float sWs1c[3*HH];
    __shared__ float sLng[HH], sLnb[HH], sWs2v[HH], sBs1[HH];
    int t = threadIdx.x;
    for (int i = t; i < 3*HH; i += 256) sWs1c[i] = Ws1[HH*HH + i];
    if (t < HH) { sLng[t] = lng[t]; sLnb[t] = lnb[t]; sWs2v[t] = Ws2[t]; sBs1[t] = bs1[t]; }
    __syncthreads();

    int e = blockIdx.x * 256 + t;
    int src = e >> 5;

    const int* eiw = (const int*)ei;
    int tgt;
    if (eiw[65] == 0) tgt = (int)(((const long long*)ei)[EE + e]);
    else              tgt = eiw[EE + e];

    float a0 = attr[e*3+0], a1 = attr[e*3+1], a2 = attr[e*3+2];

    const float4* SAh4 = (const float4*)(g_SAhi + src*HH);
    const float4* SAl4 = (const float4*)(g_SAlo + src*HH);
    const float4* SBh4 = (const float4*)(g_SBhi + (size_t)tgt*HH);
    const float4* SBl4 = (const float4*)(g_SBlo + (size_t)tgt*HH);
    const float4* c0   = (const float4*)sWs1c;
    const float4* c1   = (const float4*)(sWs1c + HH);
    const float4* c2   = (const float4*)(sWs1c + 2*HH);
    const float4* bb4  = (const float4*)sBs1;

    float4 h4[32];
    float ms = 0.f, mc = 0.f;     // Kahan mean accumulator
    #pragma unroll
    for (int q = 0; q < 32; q++) {
        float4 sh = SAh4[q], sl = SAl4[q], th = SBh4[q], tl = SBl4[q];
        float4 w0 = c0[q], w1 = c1[q], w2 = c2[q], bb = bb4[q];
        float4 v;
        v.x = comp_h(sh.x, sl.x, th.x, tl.x, a0,w0.x, a1,w1.x, a2,w2.x, bb.x);
        v.y = comp_h(sh.y, sl.y, th.y, tl.y, a0,w0.y, a1,w1.y, a2,w2.y, bb.y);
        v.z = comp_h(sh.z, sl.z, th.z, tl.z, a0,w0.z, a1,w1.z, a2,w2.z, bb.z);
        v.w = comp_h(sh.w, sl.w, th.w, tl.w, a0,w0.w, a1,w1.w, a2,w2.w, bb.w);
        h4[q] = v;
        kadd(ms, mc, v.x); kadd(ms, mc, v.y); kadd(ms, mc, v.z); kadd(ms, mc, v.w);
    }
    float mu = __fmul_rn(__fadd_rn(ms, mc), 0.0078125f);   // /128 exact scale
    float vs = 0.f, vc = 0.f;
    #pragma unroll
    for (int q = 0; q < 32; q++) {
        float d;
        d = __fsub_rn(h4[q].x, mu); kprodadd(vs, vc, d, d);
        d = __fsub_rn(h4[q].y, mu); kprodadd(vs, vc, d, d);
        d = __fsub_rn(h4[q].z, mu); kprodadd(vs, vc, d, d);
        d = __fsub_rn(h4[q].w, mu); kprodadd(vs, vc, d, d);
    }
    float var = __fmul_rn(__fadd_rn(vs, vc), 0.0078125f);
    float vpe = __fadd_rn(var, 1e-5f);
    float rstd = (float)(1.0 / sqrt((double)vpe));          // correctly-rounded rsqrt

    float rs = 0.f, rc = 0.f;     // Kahan for raw dot
    const float4* g4 = (const float4*)sLng;
    const float4* b4 = (const float4*)sLnb;
    const float4* s4 = (const float4*)sWs2v;
    #pragma unroll
    for (int q = 0; q < 32; q++) {
        float4 gg = g4[q], bb = b4[q], ww = s4[q];
        float u;
        u = __fadd_rn(__fmul_rn(__fmul_rn(__fsub_rn(h4[q].x, mu), rstd), gg.x), bb.x);
        u = (u >= 0.f) ? u : __fmul_rn(NEG, u); kprodadd(rs, rc, u, ww.x);
        u = __fadd_rn(__fmul_rn(__fmul_rn(__fsub_rn(h4[q].y, mu), rstd), gg.y), bb.y);
        u = (u >= 0.f) ? u : __fmul_rn(NEG, u); kprodadd(rs, rc, u, ww.y);
        u = __fadd_rn(__fmul_rn(__fmul_rn(__fsub_rn(h4[q].z, mu), rstd), gg.z), bb.z);
        u = (u >= 0.f) ? u : __fmul_rn(NEG, u); kprodadd(rs, rc, u, ww.z);
        u = __fadd_rn(__fmul_rn(__fmul_rn(__fsub_rn(h4[q].w, mu), rstd), gg.w), bb.w);
        u = (u >= 0.f) ? u : __fmul_rn(NEG, u); kprodadd(rs, rc, u, ww.w);
    }
    kadd(rs, rc, bs2[0]);
    g_raw[e] = __fadd_rn(rs, rc);
}

// ------------------------- kernel E2: gating GEMM + row finale --------------
// smem layout (floats)
#define OFF_W     0              // [128][192] = 24576
#define OFF_EHC   24576          // union: eh tile [128][68] (8704) / sC [64][193] (12352)
#define OFF_WPC   36928          // Wp rows 128..130 [3][128]
#define OFF_BG1   37312          // [192]
#define OFF_WG2   37504          // [192]
#define OFF_ATTR  37696          // [64][3]
#define OFF_LOGIT 37888          // [64]
#define OFF_TGT   37952          // [64] int
#define OFF_GATE  38016          // [64][3] double = 384 floats
#define G_SMEM_FLOATS 38400

__global__ void __launch_bounds__(256, 1)
gate_kernel(const void* __restrict__ ei, const float* __restrict__ attr,
            const float* __restrict__ Wp,
            const float* __restrict__ bg1, const float* __restrict__ Wg2,
            const float* __restrict__ bg2,
            float* __restrict__ out, int out_size)
{
    extern __shared__ float sm[];
    float*  sW    = sm + OFF_W;
    float*  sEh   = sm + OFF_EHC;      // during mainloop
    float*  sC    = sm + OFF_EHC;      // during epilogue (overlay)
    float*  sWpc  = sm + OFF_WPC;
    float*  sbg1  = sm + OFF_BG1;
    float*  sWg2  = sm + OFF_WG2;
    float*  sAttr = sm + OFF_ATTR;
    float*  sLog  = sm + OFF_LOGIT;
    int*    sTgt  = (int*)(sm + OFF_TGT);
    double* sGate = (double*)(sm + OFF_GATE);

    int t = threadIdx.x;
    int e0 = blockIdx.x * 64;

    // ---- stage weights + params ----
    {
        const float4* wsrc = (const float4*)g_Wg1KM;
        float4* wdst = (float4*)sW;
        for (int i = t; i < (HH*192)/4; i += 256) wdst[i] = wsrc[i];
        for (int i = t; i < 3*HH; i += 256) sWpc[i] = Wp[HH*HH + i];
        if (t < 192) { sbg1[t] = bg1[t]; sWg2[t] = Wg2[t]; sAttr[t] = attr[e0*3 + t]; }
        if (t < 64) {
            const int* eiw = (const int*)ei;
            int e = e0 + t;
            int tg;
            if (eiw[65] == 0) tg = (int)(((const long long*)ei)[EE + e]);
            else              tg = eiw[EE + e];
            sTgt[t] = tg;
        }
    }
    __syncthreads();

    // ---- stage eh tile [k][e] (recomputed, bit-identical formula) ----
    {
        int es = t & 63, part = t >> 6;
        int tg = sTgt[es];
        int srcn = (e0 + es) >> 5;
        float a0 = sAttr[es*3+0], a1 = sAttr[es*3+1], a2 = sAttr[es*3+2];
        const float4* PB4 = (const float4*)(g_PB + (size_t)tg*HH);
        const float4* PA4 = (const float4*)(g_PA + (size_t)srcn*HH);
        const float4* p0  = (const float4*)sWpc;
        const float4* p1  = (const float4*)(sWpc + HH);
        const float4* p2  = (const float4*)(sWpc + 2*HH);
        #pragma unroll
        for (int i = 0; i < 8; i++) {
            int c = part*8 + i;            // float4 chunk -> k = 4c
            float4 pa = PA4[c], pb = PB4[c];
            float4 w0 = p0[c], w1 = p1[c], w2 = p2[c];
            float4 v;
            v.x = fmaxf(pa.x + pb.x + fmaf(a0, w0.x, fmaf(a1, w1.x, a2*w2.x)), 0.f);
            v.y = fmaxf(pa.y + pb.y + fmaf(a0, w0.y, fmaf(a1, w1.y, a2*w2.y)), 0.f);
            v.z = fmaxf(pa.z + pb.z + fmaf(a0, w0.z, fmaf(a1, w1.z, a2*w2.z)), 0.f);
            v.w = fmaxf(pa.w + pb.w + fmaf(a0, w0.w, fmaf(a1, w1.w, a2*w2.w)), 0.f);
            int k = 4*c;
            sEh[(k+0)*68 + es] = v.x;
            sEh[(k+1)*68 + es] = v.y;
            sEh[(k+2)*68 + es] = v.z;
            sEh[(k+3)*68 + es] = v.w;
        }
    }
    __syncthreads();

    // ---- main GEMM: each thread = 4 edges x 6 m-pairs, packed f32x2 --------
    int tx = t & 15;       // m-pair column: pairs (2tx+32j, 2tx+32j+1)
    int ty = t >> 4;       // edge group: edges 4ty..4ty+3
    ull acc[24];
    #pragma unroll
    for (int jp = 0; jp < 6; jp++) {
        int m = 2*tx + 32*jp;
        ull b = pack2(sbg1[m], sbg1[m+1]);
        #pragma unroll
        for (int e2 = 0; e2 < 4; e2++) acc[jp*4+e2] = b;
    }
    {
        const float* ehp = sEh + 4*ty;
        const float* wp  = sW + 2*tx;
        #pragma unroll 4
        for (int k = 0; k < HH; k++) {
            float4 ev = *(const float4*)(ehp + k*68);
            ull ed0 = pack2(ev.x, ev.x);
            ull ed1 = pack2(ev.y, ev.y);
            ull ed2 = pack2(ev.z, ev.z);
            ull ed3 = pack2(ev.w, ev.w);
            const float* wk = wp + k*192;
            #pragma unroll
            for (int jp = 0; jp < 6; jp++) {
                ull w = *(const ull*)(wk + 32*jp);
                FFMA2(acc[jp*4+0], ed0, w);
                FFMA2(acc[jp*4+1], ed1, w);
                FFMA2(acc[jp*4+2], ed2, w);
                FFMA2(acc[jp*4+3], ed3, w);
            }
        }
    }
    __syncthreads();   // eh tile dead; overlay sC

    // ---- write relu'd hidden to sC [e][193] --------------------------------
    #pragma unroll
    for (int jp = 0; jp < 6; jp++) {
        int m = 2*tx + 32*jp;
        #pragma unroll
        for (int e2 = 0; e2 < 4; e2++) {
            float2 c = unpack2(acc[jp*4+e2]);
            int e = 4*ty + e2;
            sC[e*193 + m]     = fmaxf(c.x, 0.f);
            sC[e*193 + m + 1] = fmaxf(c.y, 0.f);
        }
    }
    __syncthreads();

    // ---- per-(edge, r): ascending-m fmaf reduction + sigmoid (exact order) -
    if (t < 192) {
        int e = t / 3, r = t - 3*(t/3);
        const float* row = sC + e*193 + r*64;
        const float* wg  = sWg2 + r*64;
        float gs = 0.f;
        #pragma unroll
        for (int mm = 0; mm < 64; mm++) gs = fmaf(row[mm], wg[mm], gs);
        double z = (double)gs + (double)bg2[r];
        sGate[e*3 + r] = 1.0/(1.0 + exp(-z));
    }
    __syncthreads();

    // ---- per-edge: combine regimes, score, logit ---------------------------
    if (t < 64) {
        double gc = 0.0;
        #pragma unroll
        for (int r = 0; r < RR; r++) gc += sGate[t*3 + r] * g_rp[r];
        float raw = g_raw[e0 + t];
        float score = __fmul_rn(__fmul_rn(raw, (float)gc), (float)g_amp);
        sLog[t] = __fdiv_rn(score, 0.3f);
    }
    __syncthreads();

    // ---- row finale: warps 0,1 handle the 2 source rows of this tile -------
    if (t < 64) {
        int w = t >> 5, lane = t & 31;
        int srcRow = (e0 >> 5) + w;
        int tgt = sTgt[t];
        float logit = sLog[t];

        const unsigned full = 0xffffffffu;
        unsigned dupm = __match_any_sync(full, tgt);
        int leader = 31 - __clz(dupm);          // highest lane = last edge wins
        bool valid = (lane == leader);
        unsigned vmask = __ballot_sync(full, valid);

        float lv = valid ? logit : -3.4e38f;
        float mx = lv;
        #pragma unroll
        for (int o = 16; o; o >>= 1) mx = fmaxf(mx, __shfl_xor_sync(full, mx, o));
        float evf = 0.f;
        if (valid) {
            float d = __fsub_rn(logit, mx);
            evf = (float)exp((double)d);
        }
        double sumd = (double)evf;
        #pragma unroll
        for (int o = 16; o; o >>= 1) sumd += __shfl_xor_sync(full, sumd, o);

        unsigned long long occ = (tgt < 64) ? (1ull << tgt) : 0ull;
        #pragma unroll
        for (int o = 16; o; o >>= 1) occ |= __shfl_xor_sync(full, occ, o);

        float p; int idx;
        if (valid) {
            p = (float)((double)evf / sumd);
            idx = tgt;
        } else {
            int q = __popc(~vmask & ((1u << lane) - 1u));
            unsigned long long miss = ~occ;
            unsigned lo = (unsigned)miss;
            int pl = __popc(lo);
            unsigned word; int base2; int cnt = q;
            if (cnt < pl) { word = lo; base2 = 0; }
            else { word = (unsigned)(miss >> 32); base2 = 32; cnt -= pl; }
            while (cnt > 0) { word &= word - 1u; cnt--; }
            idx = base2 + (__ffs(word) - 1);
            p = 0.f;
        }

        // bitonic sort 32 lanes: value desc, tie -> smaller index
        #pragma unroll
        for (int k = 2; k <= 32; k <<= 1) {
            #pragma unroll
            for (int jj = k >> 1; jj > 0; jj >>= 1) {
                float p2 = __shfl_xor_sync(full, p, jj);
                int   i2 = __shfl_xor_sync(full, idx, jj);
                bool mineBetter = (p > p2) || (p == p2 && idx < i2);
                bool lower = ((lane & jj) == 0);
                bool up    = ((lane & k) == 0);
                bool keepBetter = (lower == up);
                if (keepBetter != mineBetter) { p = p2; idx = i2; }
            }
        }

        float wv = (p > 1e-6f) ? p : 0.f;
        int o0 = srcRow * KK + lane;
        out[o0] = wv;
        if (out_size >= 2*NN*KK) out[NN*KK + o0] = (float)idx;
    }
}

// ------------------------- launch ------------------------------------------
extern "C" void kernel_launch(void* const* d_in, const int* in_sizes, int n_in,
                              void* d_out, int out_size)
{
    const float* x   = (const float*)d_in[0];
    const void*  ei  = d_in[1];
    const float* att = (const float*)d_in[2];
    const float* Ws1 = (const float*)d_in[3];
    const float* bs1 = (const float*)d_in[4];
    const float* lng = (const float*)d_in[5];
    const float* lnb = (const float*)d_in[6];
    const float* Ws2 = (const float*)d_in[7];
    const float* bs2 = (const float*)d_in[8];
    const float* Wp  = (const float*)d_in[9];
    const float* bp  = (const float*)d_in[10];
    const float* Wr1 = (const float*)d_in[11];
    const float* br1 = (const float*)d_in[12];
    const float* Wr2 = (const float*)d_in[13];
    const float* br2 = (const float*)d_in[14];
    const float* Wg1 = (const float*)d_in[15];
    const float* bg1 = (const float*)d_in[16];
    const float* Wg2 = (const float*)d_in[17];
    const float* bg2 = (const float*)d_in[18];
    const float* Wc1 = (const float*)d_in[19];
    const float* bc1 = (const float*)d_in[20];
    const float* Wc2 = (const float*)d_in[21];
    const float* bc2 = (const float*)d_in[22];

    cudaFuncSetAttribute(gate_kernel, cudaFuncAttributeMaxDynamicSharedMemorySize,
                         G_SMEM_FLOATS * (int)sizeof(float));

    stats_kernel<<<128, 128>>>(x, Wc1, bc1, Wc2, bc2);
    setup_kernel<<<1, 128>>>(Wr1, br1, Wr2, br2, Wg1);
    node_pre_kernel<<<1024, 256>>>(x, Ws1, Wp, bp);
    scorer_kernel<<<1024, 256>>>(ei, att, Ws1, lng, lnb, Ws2, bs2, bs1);
    gate_kernel<<<EE/64, 256, G_SMEM_FLOATS * sizeof(float)>>>(
        ei, att, Wp, bg1, Wg2, bg2, (float*)d_out, out_size);
}